// round 7
// baseline (speedup 1.0000x reference)
#include <cuda_runtime.h>
#include <math.h>

#define BATCH 64
#define SEQ   2048
#define DIN   256
#define DOUT  256
#define MTOT  (BATCH * SEQ)

#define NSCAN   64
#define NWORK   84
#define NCTA    (NSCAN + NWORK)      // 148 CTAs = one per SM
#define CHUNK   64
#define NCHUNK  (SEQ / CHUNK)        // 32
#define NTILES  (NCHUNK * BATCH * 4) // 8192 64x64 tiles

#define KREG 192
#define KSM  (DOUT - KREG)           // 64
#define NGREG (KREG / 4)             // 48 register-weight groups
#define NGSM  (KSM / 4)              // 16 global-weight groups

// smem: scan needs only hbuf [2][DOUT]; gemm needs 4416 floats. Take max.
#define GEMM_SMEM_FLOATS (64 * 36 + 32 * 64 + 64)
#define SMEM_BYTES (GEMM_SMEM_FLOATS * (int)sizeof(float))   // 17664 > 2KB scan

__device__ int   g_flags[BATCH * NCHUNK];
__device__ float g_WhT[DOUT * KSM];      // [j][k'] : W_h[KREG+k'][j], 64KB

// Prep: reset flags + transpose W_h tail into g_WhT (both tiny).
__global__ void prep_kernel(const float* __restrict__ Wh)
{
    int i = blockIdx.x * blockDim.x + threadIdx.x;
    if (i < BATCH * NCHUNK) g_flags[i] = 0;
    // 16384 transpose elements
    for (int e = i; e < DOUT * KSM; e += gridDim.x * blockDim.x) {
        int jj = e / KSM, kk = e % KSM;
        g_WhT[e] = Wh[(KREG + kk) * DOUT + jj];
    }
}

__device__ __forceinline__ int ld_acquire_gpu(const int* p)
{
    int v;
    asm volatile("ld.acquire.gpu.global.b32 %0, [%1];"
                 : "=r"(v) : "l"(p) : "memory");
    return v;
}

// ---------------------------------------------------------------------------
// Bit-exact replica of XLA's EmitFastTanh (Eigen fast tanh, FMA variant).
// ---------------------------------------------------------------------------
__device__ __forceinline__ float xla_tanh(float x)
{
    const float kClamp = 7.99881172180175781f;
    const float kTiny  = 0.0004f;
    const float a1  = 4.89352455891786e-03f;
    const float a3  = 6.37261928875436e-04f;
    const float a5  = 1.48572235717979e-05f;
    const float a7  = 5.12229709037114e-08f;
    const float a9  = -8.60467152213735e-11f;
    const float a11 = 2.00018790482477e-13f;
    const float a13 = -2.76076847742355e-16f;
    const float b0  = 4.89352518554385e-03f;
    const float b2  = 2.26843463243900e-03f;
    const float b4  = 1.18534705686654e-04f;
    const float b6  = 1.19825839466702e-06f;

    float ax = fabsf(x);
    float xc = fminf(fmaxf(x, -kClamp), kClamp);
    float x2 = __fmul_rn(xc, xc);

    float p = __fmaf_rn(x2, a13, a11);
    p = __fmaf_rn(x2, p, a9);
    p = __fmaf_rn(x2, p, a7);
    p = __fmaf_rn(x2, p, a5);
    p = __fmaf_rn(x2, p, a3);
    p = __fmaf_rn(x2, p, a1);
    p = __fmul_rn(xc, p);

    float q = __fmaf_rn(x2, b6, b4);
    q = __fmaf_rn(x2, q, b2);
    q = __fmaf_rn(x2, q, b0);

    float r = __fdiv_rn(p, q);
    return (ax < kTiny) ? x : r;
}

// ---------------------------------------------------------------------------
// GEMM producer: zx = input @ W_x + (b_x+b_h), 64x64 tiles in time order.
// Bit-exact: single fp32 accumulator, ascending k, fused FMA.
// ---------------------------------------------------------------------------
__device__ void gemm_worker(
    float* sm, int worker,
    const float* __restrict__ A,
    const float* __restrict__ W,
    const float* __restrict__ b_h,
    const float* __restrict__ b_x,
    float* __restrict__ C)
{
    float* As   = sm;                // [64][36]
    float* Bs   = sm + 64 * 36;      // [32][64]
    float* bias = sm + 64 * 36 + 32 * 64;

    const int tid = threadIdx.x;
    const int tx = tid & 15;
    const int ty = tid >> 4;

    for (int tau = worker; tau < NTILES; tau += NWORK) {
        const int c  = tau >> 8;
        const int r  = tau & 255;
        const int bb = r >> 2;
        const int nq = r & 3;
        const long m0 = (long)bb * SEQ + (long)c * CHUNK;
        const int n0 = nq * 64;

        if (tid < 64) bias[tid] = __fadd_rn(b_h[n0 + tid], b_x[n0 + tid]);

        float acc[16];
#pragma unroll
        for (int i = 0; i < 16; ++i) acc[i] = 0.f;

        for (int kc = 0; kc < DIN; kc += 32) {
            __syncthreads();
            {
                int i0 = tid, i1 = tid + 256;
                int r0 = i0 >> 3, c0 = (i0 & 7) << 2;
                int r1 = i1 >> 3, c1 = (i1 & 7) << 2;
                float4 v0 = __ldcs((const float4*)(A + (m0 + r0) * DIN + kc + c0));
                float4 v1 = __ldcs((const float4*)(A + (m0 + r1) * DIN + kc + c1));
                As[r0 * 36 + c0 + 0] = v0.x; As[r0 * 36 + c0 + 1] = v0.y;
                As[r0 * 36 + c0 + 2] = v0.z; As[r0 * 36 + c0 + 3] = v0.w;
                As[r1 * 36 + c1 + 0] = v1.x; As[r1 * 36 + c1 + 1] = v1.y;
                As[r1 * 36 + c1 + 2] = v1.z; As[r1 * 36 + c1 + 3] = v1.w;
            }
            {
                int i0 = tid, i1 = tid + 256;
                int k0 = i0 >> 4, g0 = (i0 & 15) << 2;
                int k1 = i1 >> 4, g1 = (i1 & 15) << 2;
                *(float4*)(Bs + k0 * 64 + g0) =
                    *(const float4*)(W + (kc + k0) * DOUT + n0 + g0);
                *(float4*)(Bs + k1 * 64 + g1) =
                    *(const float4*)(W + (kc + k1) * DOUT + n0 + g1);
            }
            __syncthreads();

#pragma unroll
            for (int k = 0; k < 32; ++k) {
                float4 b4 = *(const float4*)(Bs + k * 64 + (tx << 2));
                float a0 = As[(ty * 4 + 0) * 36 + k];
                float a1 = As[(ty * 4 + 1) * 36 + k];
                float a2 = As[(ty * 4 + 2) * 36 + k];
                float a3 = As[(ty * 4 + 3) * 36 + k];
                acc[ 0] = __fmaf_rn(a0, b4.x, acc[ 0]);
                acc[ 1] = __fmaf_rn(a0, b4.y, acc[ 1]);
                acc[ 2] = __fmaf_rn(a0, b4.z, acc[ 2]);
                acc[ 3] = __fmaf_rn(a0, b4.w, acc[ 3]);
                acc[ 4] = __fmaf_rn(a1, b4.x, acc[ 4]);
                acc[ 5] = __fmaf_rn(a1, b4.y, acc[ 5]);
                acc[ 6] = __fmaf_rn(a1, b4.z, acc[ 6]);
                acc[ 7] = __fmaf_rn(a1, b4.w, acc[ 7]);
                acc[ 8] = __fmaf_rn(a2, b4.x, acc[ 8]);
                acc[ 9] = __fmaf_rn(a2, b4.y, acc[ 9]);
                acc[10] = __fmaf_rn(a2, b4.z, acc[10]);
                acc[11] = __fmaf_rn(a2, b4.w, acc[11]);
                acc[12] = __fmaf_rn(a3, b4.x, acc[12]);
                acc[13] = __fmaf_rn(a3, b4.y, acc[13]);
                acc[14] = __fmaf_rn(a3, b4.z, acc[14]);
                acc[15] = __fmaf_rn(a3, b4.w, acc[15]);
            }
        }

#pragma unroll
        for (int i = 0; i < 4; ++i) {
            float4 o;
            o.x = __fadd_rn(acc[i * 4 + 0], bias[(tx << 2) + 0]);
            o.y = __fadd_rn(acc[i * 4 + 1], bias[(tx << 2) + 1]);
            o.z = __fadd_rn(acc[i * 4 + 2], bias[(tx << 2) + 2]);
            o.w = __fadd_rn(acc[i * 4 + 3], bias[(tx << 2) + 3]);
            __stcs((float4*)(C + (m0 + ty * 4 + i) * DOUT + n0 + (tx << 2)), o);
        }

        __threadfence();
        __syncthreads();
        if (tid == 0) atomicAdd(&g_flags[bb * NCHUNK + c], 1);
    }
}

// ---------------------------------------------------------------------------
// Fused kernel. Scan CTAs [0,64): thread j owns column j.
// Weights: rows 0..191 in registers; rows 192..255 via L1-resident LDG.128
// from the transposed g_WhT (zero smem-crossbar cost). h broadcasts are the
// only crossbar traffic. Strict single-accumulator ascending-k FMA chain.
// ---------------------------------------------------------------------------
__global__ __launch_bounds__(256, 1) void rnn_fused_kernel(
    const float* __restrict__ input,
    const float* __restrict__ h0,
    const float* __restrict__ Wh,
    const float* __restrict__ Wx,
    const float* __restrict__ b_h,
    const float* __restrict__ b_x,
    float* __restrict__ y,
    float* __restrict__ hfin)
{
    extern __shared__ float sm[];

    if (blockIdx.x >= NSCAN) {
        gemm_worker(sm, blockIdx.x - NSCAN, input, Wx, b_h, b_x, y);
        return;
    }

    float* hbuf = sm;                 // [2][DOUT]

    const int b = blockIdx.x;
    const int j = threadIdx.x;

    float w[KREG];
#pragma unroll
    for (int kk = 0; kk < KREG; ++kk)
        w[kk] = Wh[kk * DOUT + j];

    hbuf[j] = h0[b * DOUT + j];

    float* yb = y + (size_t)b * SEQ * DOUT;
    const float4* wg4 = (const float4*)(g_WhT + j * KSM);  // 16 float4, L1-hot
    int cur = 0;

    for (int c = 0; c < NCHUNK; ++c) {
        if (j == 0) {
            while (ld_acquire_gpu(&g_flags[b * NCHUNK + c]) != 4) { }
        }
        __syncthreads();

#pragma unroll 1
        for (int ti = 0; ti < CHUNK; ++ti) {
            const int t = c * CHUNK + ti;
            float zx = yb[(size_t)t * DOUT + j];

            const float4* h4 = (const float4*)(hbuf + cur * DOUT);
            float acc = 0.f;

            // groups 0..43: register weights
#pragma unroll
            for (int g = 0; g < NGREG - 4; ++g) {
                float4 hv = h4[g];
                acc = __fmaf_rn(hv.x, w[4 * g + 0], acc);
                acc = __fmaf_rn(hv.y, w[4 * g + 1], acc);
                acc = __fmaf_rn(hv.z, w[4 * g + 2], acc);
                acc = __fmaf_rn(hv.w, w[4 * g + 3], acc);
            }

            // prefetch first 4 tail-weight quads (~4 groups = 64 cyc ahead)
            float4 wq0 = __ldg(wg4 + 0);
            float4 wq1 = __ldg(wg4 + 1);
            float4 wq2 = __ldg(wg4 + 2);
            float4 wq3 = __ldg(wg4 + 3);

            // groups 44..47: register weights
#pragma unroll
            for (int g = NGREG - 4; g < NGREG; ++g) {
                float4 hv = h4[g];
                acc = __fmaf_rn(hv.x, w[4 * g + 0], acc);
                acc = __fmaf_rn(hv.y, w[4 * g + 1], acc);
                acc = __fmaf_rn(hv.z, w[4 * g + 2], acc);
                acc = __fmaf_rn(hv.w, w[4 * g + 3], acc);
            }

            // tail groups 0..15: global weights, 4-deep rotation
#pragma unroll
            for (int g = 0; g < NGSM; ++g) {
                float4 hv = h4[NGREG + g];
                float4 wv;
                if ((g & 3) == 0) wv = wq0;
                else if ((g & 3) == 1) wv = wq1;
                else if ((g & 3) == 2) wv = wq2;
                else wv = wq3;
                if (g + 4 < NGSM) {
                    float4 nw = __ldg(wg4 + g + 4);
                    if ((g & 3) == 0) wq0 = nw;
                    else if ((g & 3) == 1) wq1 = nw;
                    else if ((g & 3) == 2) wq2 = nw;
                    else wq3 = nw;
                }
                acc = __fmaf_rn(hv.x, wv.x, acc);
                acc = __fmaf_rn(hv.y, wv.y, acc);
                acc = __fmaf_rn(hv.z, wv.z, acc);
                acc = __fmaf_rn(hv.w, wv.w, acc);
            }

            float v = xla_tanh(__fadd_rn(acc, zx));
            hbuf[(cur ^ 1) * DOUT + j] = v;
            __stcs(&yb[(size_t)t * DOUT + j], v);   // before the barrier
            __syncthreads();
            cur ^= 1;
        }
    }

    hfin[b * DOUT + j] = hbuf[cur * DOUT + j];
}

// ---------------------------------------------------------------------------
extern "C" void kernel_launch(void* const* d_in, const int* in_sizes, int n_in,
                              void* d_out, int out_size)
{
    const float* input = (const float*)d_in[0];
    const float* h0    = (const float*)d_in[1];
    const float* W_h   = (const float*)d_in[2];
    const float* W_x   = (const float*)d_in[3];
    const float* b_h   = (const float*)d_in[4];
    const float* b_x   = (const float*)d_in[5];

    float* y    = (float*)d_out;
    float* hfin = y + (size_t)BATCH * SEQ * DOUT;

    cudaFuncSetAttribute(rnn_fused_kernel,
                         cudaFuncAttributeMaxDynamicSharedMemorySize,
                         SMEM_BYTES);

    prep_kernel<<<32, 256>>>(W_h);
    rnn_fused_kernel<<<NCTA, 256, SMEM_BYTES>>>(
        input, h0, W_h, W_x, b_h, b_x, y, hfin);
}

// round 8
// speedup vs baseline: 3.0241x; 3.0241x over previous
#include <cuda_runtime.h>
#include <math.h>

#define BATCH 64
#define SEQ   2048
#define DIN   256
#define DOUT  256
#define MTOT  (BATCH * SEQ)

#define NSCAN   64
#define NWORK   64
#define NCTA    (NSCAN + NWORK)      // 128 CTAs, all wave-1 resident
#define CHUNK   64
#define NCHUNK  (SEQ / CHUNK)        // 32
#define NTILES  (NCHUNK * BATCH * 4) // 8192 64x64 tiles

#define KREG 192
#define KSM  (DOUT - KREG)           // 64
#define WSTRIDE 68                   // 17 float4/column: conflict-free LDS.128
#define SCAN_SMEM_FLOATS (DOUT * WSTRIDE + 2 * DOUT)
#define SMEM_BYTES (SCAN_SMEM_FLOATS * (int)sizeof(float))   // 71680

// named barriers: producers(128 threads) arrive + all(256) sync = 384 counts
#define BAR_LO 1
#define BAR_HI 2
#define BAR_CNT 384

__device__ int g_flags[BATCH * NCHUNK];

__global__ void reset_flags_kernel()
{
    int i = blockIdx.x * blockDim.x + threadIdx.x;
    if (i < BATCH * NCHUNK) g_flags[i] = 0;
}

__device__ __forceinline__ int ld_acquire_gpu(const int* p)
{
    int v;
    asm volatile("ld.acquire.gpu.global.b32 %0, [%1];"
                 : "=r"(v) : "l"(p) : "memory");
    return v;
}

__device__ __forceinline__ void bar_arrive(int b)
{
    asm volatile("bar.arrive %0, %1;" :: "r"(b), "r"(BAR_CNT) : "memory");
}
__device__ __forceinline__ void bar_wait(int b)
{
    asm volatile("bar.sync %0, %1;" :: "r"(b), "r"(BAR_CNT) : "memory");
}

// ---------------------------------------------------------------------------
// Bit-exact replica of XLA's EmitFastTanh (Eigen fast tanh, FMA variant).
// ---------------------------------------------------------------------------
__device__ __forceinline__ float xla_tanh(float x)
{
    const float kClamp = 7.99881172180175781f;
    const float kTiny  = 0.0004f;
    const float a1  = 4.89352455891786e-03f;
    const float a3  = 6.37261928875436e-04f;
    const float a5  = 1.48572235717979e-05f;
    const float a7  = 5.12229709037114e-08f;
    const float a9  = -8.60467152213735e-11f;
    const float a11 = 2.00018790482477e-13f;
    const float a13 = -2.76076847742355e-16f;
    const float b0  = 4.89352518554385e-03f;
    const float b2  = 2.26843463243900e-03f;
    const float b4  = 1.18534705686654e-04f;
    const float b6  = 1.19825839466702e-06f;

    float ax = fabsf(x);
    float xc = fminf(fmaxf(x, -kClamp), kClamp);
    float x2 = __fmul_rn(xc, xc);

    float p = __fmaf_rn(x2, a13, a11);
    p = __fmaf_rn(x2, p, a9);
    p = __fmaf_rn(x2, p, a7);
    p = __fmaf_rn(x2, p, a5);
    p = __fmaf_rn(x2, p, a3);
    p = __fmaf_rn(x2, p, a1);
    p = __fmul_rn(xc, p);

    float q = __fmaf_rn(x2, b6, b4);
    q = __fmaf_rn(x2, q, b2);
    q = __fmaf_rn(x2, q, b0);

    float r = __fdiv_rn(p, q);
    return (ax < kTiny) ? x : r;
}

// ---------------------------------------------------------------------------
// GEMM producer: zx = input @ W_x + (b_x+b_h), 64x64 tiles in time order.
// Bit-exact: single fp32 accumulator, ascending k, fused FMA.
// ---------------------------------------------------------------------------
__device__ void gemm_worker(
    float* sm, int worker,
    const float* __restrict__ A,
    const float* __restrict__ W,
    const float* __restrict__ b_h,
    const float* __restrict__ b_x,
    float* __restrict__ C)
{
    float* As   = sm;                // [64][36]
    float* Bs   = sm + 64 * 36;      // [32][64]
    float* bias = sm + 64 * 36 + 32 * 64;

    const int tid = threadIdx.x;
    const int tx = tid & 15;
    const int ty = tid >> 4;

    for (int tau = worker; tau < NTILES; tau += NWORK) {
        const int c  = tau >> 8;
        const int r  = tau & 255;
        const int bb = r >> 2;
        const int nq = r & 3;
        const long m0 = (long)bb * SEQ + (long)c * CHUNK;
        const int n0 = nq * 64;

        if (tid < 64) bias[tid] = __fadd_rn(b_h[n0 + tid], b_x[n0 + tid]);

        float acc[16];
#pragma unroll
        for (int i = 0; i < 16; ++i) acc[i] = 0.f;

        for (int kc = 0; kc < DIN; kc += 32) {
            __syncthreads();
            {
                int i0 = tid, i1 = tid + 256;
                int r0 = i0 >> 3, c0 = (i0 & 7) << 2;
                int r1 = i1 >> 3, c1 = (i1 & 7) << 2;
                float4 v0 = __ldcs((const float4*)(A + (m0 + r0) * DIN + kc + c0));
                float4 v1 = __ldcs((const float4*)(A + (m0 + r1) * DIN + kc + c1));
                As[r0 * 36 + c0 + 0] = v0.x; As[r0 * 36 + c0 + 1] = v0.y;
                As[r0 * 36 + c0 + 2] = v0.z; As[r0 * 36 + c0 + 3] = v0.w;
                As[r1 * 36 + c1 + 0] = v1.x; As[r1 * 36 + c1 + 1] = v1.y;
                As[r1 * 36 + c1 + 2] = v1.z; As[r1 * 36 + c1 + 3] = v1.w;
            }
            {
                int i0 = tid, i1 = tid + 256;
                int k0 = i0 >> 4, g0 = (i0 & 15) << 2;
                int k1 = i1 >> 4, g1 = (i1 & 15) << 2;
                *(float4*)(Bs + k0 * 64 + g0) =
                    *(const float4*)(W + (kc + k0) * DOUT + n0 + g0);
                *(float4*)(Bs + k1 * 64 + g1) =
                    *(const float4*)(W + (kc + k1) * DOUT + n0 + g1);
            }
            __syncthreads();

#pragma unroll
            for (int k = 0; k < 32; ++k) {
                float4 b4 = *(const float4*)(Bs + k * 64 + (tx << 2));
                float a0 = As[(ty * 4 + 0) * 36 + k];
                float a1 = As[(ty * 4 + 1) * 36 + k];
                float a2 = As[(ty * 4 + 2) * 36 + k];
                float a3 = As[(ty * 4 + 3) * 36 + k];
                acc[ 0] = __fmaf_rn(a0, b4.x, acc[ 0]);
                acc[ 1] = __fmaf_rn(a0, b4.y, acc[ 1]);
                acc[ 2] = __fmaf_rn(a0, b4.z, acc[ 2]);
                acc[ 3] = __fmaf_rn(a0, b4.w, acc[ 3]);
                acc[ 4] = __fmaf_rn(a1, b4.x, acc[ 4]);
                acc[ 5] = __fmaf_rn(a1, b4.y, acc[ 5]);
                acc[ 6] = __fmaf_rn(a1, b4.z, acc[ 6]);
                acc[ 7] = __fmaf_rn(a1, b4.w, acc[ 7]);
                acc[ 8] = __fmaf_rn(a2, b4.x, acc[ 8]);
                acc[ 9] = __fmaf_rn(a2, b4.y, acc[ 9]);
                acc[10] = __fmaf_rn(a2, b4.z, acc[10]);
                acc[11] = __fmaf_rn(a2, b4.w, acc[11]);
                acc[12] = __fmaf_rn(a3, b4.x, acc[12]);
                acc[13] = __fmaf_rn(a3, b4.y, acc[13]);
                acc[14] = __fmaf_rn(a3, b4.z, acc[14]);
                acc[15] = __fmaf_rn(a3, b4.w, acc[15]);
            }
        }

#pragma unroll
        for (int i = 0; i < 4; ++i) {
            float4 o;
            o.x = __fadd_rn(acc[i * 4 + 0], bias[(tx << 2) + 0]);
            o.y = __fadd_rn(acc[i * 4 + 1], bias[(tx << 2) + 1]);
            o.z = __fadd_rn(acc[i * 4 + 2], bias[(tx << 2) + 2]);
            o.w = __fadd_rn(acc[i * 4 + 3], bias[(tx << 2) + 3]);
            __stcs((float4*)(C + (m0 + ty * 4 + i) * DOUT + n0 + (tx << 2)), o);
        }

        __threadfence();
        __syncthreads();
        if (tid == 0) atomicAdd(&g_flags[bb * NCHUNK + c], 1);
    }
}

// ---------------------------------------------------------------------------
// Fused kernel. Scan CTAs [0,64): thread j owns column j.
// Round-6 proven body + split producer/consumer named barriers:
//   warps 0-3 produce h[0..127]  -> arrive BAR_LO after STS
//   warps 4-7 produce h[128..255]-> arrive BAR_HI after STS
//   all warps: sync BAR_LO before chain start (k=0 reads h[0..127]),
//              sync BAR_HI before group 32 (k=128 reads h[128..255]).
// High warps may finish up to ~512 cyc late without stalling anyone.
// ---------------------------------------------------------------------------
__global__ __launch_bounds__(256, 1) void rnn_fused_kernel(
    const float* __restrict__ input,
    const float* __restrict__ h0,
    const float* __restrict__ Wh,
    const float* __restrict__ Wx,
    const float* __restrict__ b_h,
    const float* __restrict__ b_x,
    float* __restrict__ y,
    float* __restrict__ hfin)
{
    extern __shared__ float sm[];

    if (blockIdx.x >= NSCAN) {
        gemm_worker(sm, blockIdx.x - NSCAN, input, Wx, b_h, b_x, y);
        return;
    }

    float* WsT  = sm;                     // [DOUT][WSTRIDE]
    float* hbuf = sm + DOUT * WSTRIDE;    // [2][DOUT]

    const int b = blockIdx.x;
    const int j = threadIdx.x;
    const int lowhalf = (j < 128);

    float w[KREG];
#pragma unroll
    for (int kk = 0; kk < KREG; ++kk)
        w[kk] = Wh[kk * DOUT + j];

#pragma unroll
    for (int i = 0; i < KSM; ++i)
        WsT[j * WSTRIDE + i] = Wh[(KREG + i) * DOUT + j];

    hbuf[j] = h0[b * DOUT + j];
    __syncthreads();                 // h0 + WsT visible
    // prime the producer barriers for step 0
    if (lowhalf) bar_arrive(BAR_LO);
    else         bar_arrive(BAR_HI);

    float* yb = y + (size_t)b * SEQ * DOUT;
    const float4* wt4 = (const float4*)(WsT + j * WSTRIDE);
    int cur = 0;

    for (int c = 0; c < NCHUNK; ++c) {
        if (j == 0) {
            while (ld_acquire_gpu(&g_flags[b * NCHUNK + c]) != 4) { }
        }
        __syncthreads();

#pragma unroll 1
        for (int ti = 0; ti < CHUNK; ++ti) {
            const int t = c * CHUNK + ti;
            float zx = yb[(size_t)t * DOUT + j];

            const float4* h4 = (const float4*)(hbuf + cur * DOUT);
            float acc = 0.f;

            bar_wait(BAR_LO);        // h[0..127] of this step ready

            // groups 0..31: k = 0..127, register weights
#pragma unroll
            for (int g = 0; g < 32; ++g) {
                float4 hv = h4[g];
                acc = __fmaf_rn(hv.x, w[4 * g + 0], acc);
                acc = __fmaf_rn(hv.y, w[4 * g + 1], acc);
                acc = __fmaf_rn(hv.z, w[4 * g + 2], acc);
                acc = __fmaf_rn(hv.w, w[4 * g + 3], acc);
            }

            bar_wait(BAR_HI);        // h[128..255] ready

            // groups 32..47: k = 128..191, register weights
#pragma unroll
            for (int g = 32; g < KREG / 4; ++g) {
                float4 hv = h4[g];
                acc = __fmaf_rn(hv.x, w[4 * g + 0], acc);
                acc = __fmaf_rn(hv.y, w[4 * g + 1], acc);
                acc = __fmaf_rn(hv.z, w[4 * g + 2], acc);
                acc = __fmaf_rn(hv.w, w[4 * g + 3], acc);
            }
            // groups 48..63: k = 192..255, transposed smem weights
#pragma unroll
            for (int g = 0; g < KSM / 4; ++g) {
                float4 hv = h4[(KREG >> 2) + g];
                float4 wv = wt4[g];
                acc = __fmaf_rn(hv.x, wv.x, acc);
                acc = __fmaf_rn(hv.y, wv.y, acc);
                acc = __fmaf_rn(hv.z, wv.z, acc);
                acc = __fmaf_rn(hv.w, wv.w, acc);
            }

            float v = xla_tanh(__fadd_rn(acc, zx));
            hbuf[(cur ^ 1) * DOUT + j] = v;
            if (lowhalf) bar_arrive(BAR_LO);   // publish ASAP after STS
            else         bar_arrive(BAR_HI);
            __stcs(&yb[(size_t)t * DOUT + j], v);
            cur ^= 1;
        }
    }

    hfin[b * DOUT + j] = hbuf[cur * DOUT + j];   // own value: no sync needed
}

// ---------------------------------------------------------------------------
extern "C" void kernel_launch(void* const* d_in, const int* in_sizes, int n_in,
                              void* d_out, int out_size)
{
    const float* input = (const float*)d_in[0];
    const float* h0    = (const float*)d_in[1];
    const float* W_h   = (const float*)d_in[2];
    const float* W_x   = (const float*)d_in[3];
    const float* b_h   = (const float*)d_in[4];
    const float* b_x   = (const float*)d_in[5];

    float* y    = (float*)d_out;
    float* hfin = y + (size_t)BATCH * SEQ * DOUT;

    cudaFuncSetAttribute(rnn_fused_kernel,
                         cudaFuncAttributeMaxDynamicSharedMemorySize,
                         SMEM_BYTES);

    reset_flags_kernel<<<8, 256>>>();
    rnn_fused_kernel<<<NCTA, 256, SMEM_BYTES>>>(
        input, h0, W_h, W_x, b_h, b_x, y, hfin);
}